// round 9
// baseline (speedup 1.0000x reference)
#include <cuda_runtime.h>
#include <math.h>

#define Bb 32
#define Ss 200
#define Hh 512
#define NCTA 128
#define ISTRIDE 292
#define WSTRIDE 36

// ------------------------- device scratch (static) -------------------------
__device__ float d_G0[6400 * 2048];     // [s][j][b] input-gate preacts + biases (52MB)
__device__ float d_h1buf[2][32 * 512];  // layer0 h, double buffered, [b][n]
__device__ float d_h2buf[2][32 * 512];  // layer1 h, double buffered, [b][n]
__device__ float d_lstm[6400 * 512];    // layer1 outputs, [(b*S+s)][n]
__device__ float d_bce[6400];
__device__ unsigned d_cnt = 0;
__device__ unsigned d_gen = 0;

__device__ __forceinline__ float sigf(float x) { return 1.f / (1.f + expf(-x)); }

// ===================== K_ingate: G0 = inp @ W_ih0^T + b =====================
// grid (16 j-tiles, 200 s), 256 threads. Tile 128j x 32b, per-thread 4x4.
__global__ __launch_bounds__(256) void K_ingate(
    const int* __restrict__ xd, const float* __restrict__ rep,
    const float* __restrict__ past, const float* __restrict__ seq,
    const float* __restrict__ emb, const float* __restrict__ Wih0,
    const float* __restrict__ bih0, const float* __restrict__ bhh0,
    const float* __restrict__ C)
{
    extern __shared__ float sh[];
    float* inp_sm = sh;                   // [32][ISTRIDE], zero-padded K: 275->288
    float* W_sm   = sh + 32 * ISTRIDE;    // [128][WSTRIDE] per k-tile
    const int t = threadIdx.x;
    const int s = blockIdx.y;
    const int j0 = blockIdx.x * 128;

    // stage input row-block for this s: [emb(x) | C * c_t], padded to 288
    for (int idx = t; idx < 32 * 288; idx += 256) {
        int b = idx / 288, k = idx % 288;
        float v = 0.f;
        if (k < 256) {
            int x = xd[b * Ss + s];
            v = emb[x * 256 + k];
        } else if (k < 275) {
            int i = k - 256;
            float craw;
            if (i < 7)       craw = rep[(b * (Ss + 1) + s) * 7 + i];
            else if (i < 13) craw = seq[(b * (Ss + 1) + s) * 6 + (i - 7)];
            else             craw = past[(b * (Ss + 1) + s) * 6 + (i - 13)];
            v = C[(b * Ss + s) * 19 + i] * craw;
        }
        inp_sm[b * ISTRIDE + k] = v;
    }

    float acc[4][4];
#pragma unroll
    for (int j = 0; j < 4; j++)
#pragma unroll
        for (int i = 0; i < 4; i++) acc[j][i] = 0.f;

    const int tx = t & 7;    // b = tx + 8*i
    const int ty = t >> 3;   // j = ty + 32*j

    for (int kt = 0; kt < 9; kt++) {
        __syncthreads();
        for (int idx = t; idx < 128 * 32; idx += 256) {
            int j = idx >> 5, kk = idx & 31, k = kt * 32 + kk;
            W_sm[j * WSTRIDE + kk] = (k < 275) ? Wih0[(j0 + j) * 275 + k] : 0.f;
        }
        __syncthreads();
#pragma unroll
        for (int k4 = 0; k4 < 8; k4++) {
            float4 a4[4], w4[4];
#pragma unroll
            for (int i = 0; i < 4; i++)
                a4[i] = *(const float4*)&inp_sm[(tx + 8 * i) * ISTRIDE + kt * 32 + k4 * 4];
#pragma unroll
            for (int j = 0; j < 4; j++)
                w4[j] = *(const float4*)&W_sm[(ty + 32 * j) * WSTRIDE + k4 * 4];
#pragma unroll
            for (int j = 0; j < 4; j++)
#pragma unroll
                for (int i = 0; i < 4; i++) {
                    acc[j][i] = fmaf(w4[j].x, a4[i].x, acc[j][i]);
                    acc[j][i] = fmaf(w4[j].y, a4[i].y, acc[j][i]);
                    acc[j][i] = fmaf(w4[j].z, a4[i].z, acc[j][i]);
                    acc[j][i] = fmaf(w4[j].w, a4[i].w, acc[j][i]);
                }
        }
    }
#pragma unroll
    for (int j = 0; j < 4; j++) {
        int jj = j0 + ty + 32 * j;
        float bias = bih0[jj] + bhh0[jj];
#pragma unroll
        for (int i = 0; i < 4; i++) {
            int b = tx + 8 * i;
            d_G0[((size_t)s * 2048 + jj) * 32 + b] = acc[j][i] + bias;
        }
    }
}

// ============================ grid barrier ==================================
__device__ __forceinline__ void gridbar(unsigned& gen)
{
    gen++;
    __syncthreads();
    __threadfence();
    if (threadIdx.x == 0) {
        unsigned a = atomicAdd(&d_cnt, 1u);
        if (a == NCTA - 1) {
            atomicExch(&d_cnt, 0u);
            __threadfence();
            atomicAdd(&d_gen, 1u);
        } else {
            while (atomicAdd(&d_gen, 0u) != gen) __nanosleep(40);
        }
    }
    __syncthreads();
    __threadfence();
}

// ========== K_recur: persistent 2-layer LSTM, software-pipelined ===========
// 768 equal-MAC gate-complete units: u<256 -> L0 (n0=2u, 8 cols x 32 b, K=512)
//                                    u>=256 -> L1 (n=u-256, 4g x 2half x 32 b, K=512)
// CTA i owns units 6i..6i+5. Superstep tau: L0 computes step tau, L1 step tau-1.
__global__ __launch_bounds__(256, 1) void K_recur(
    const float* __restrict__ Whh0, const float* __restrict__ Wih1,
    const float* __restrict__ Whh1, const float* __restrict__ bih1,
    const float* __restrict__ bhh1, const float* __restrict__ init_h,
    const float* __restrict__ init_c)
{
    extern __shared__ float sh[];
    float* bufA = sh;              // h1(prev step), [b][516]
    float* bufB = sh + 32 * 516;   // h2(prev-prev step), [b][516]
    __shared__ float g_sm[6 * 256];

    const int t = threadIdx.x, cta = blockIdx.x;
    const int b = t & 31;
    unsigned gen = atomicAdd(&d_gen, 0u);

    const bool hasL0 = (cta <= 42);
    const bool hasL1 = (cta >= 42);

    // cell state in registers of the updater threads
    float creg[6];
#pragma unroll
    for (int m = 0; m < 6; m++) {
        int u = cta * 6 + m;
        creg[m] = 0.f;
        if (u < 256) {
            if (t < 64) { int n = 2 * u + (t >> 5); creg[m] = init_c[b * 512 + n]; }
        } else {
            if (t < 32) { int n = u - 256; creg[m] = init_c[16384 + t * 512 + n]; }
        }
    }
    // init h double buffers (parity 1 = "step -1" state)
    {
        int gid = cta * 256 + t;
        if (gid < 16384) {
            d_h1buf[1][gid] = init_h[gid];
            d_h2buf[1][gid] = init_h[16384 + gid];
        }
    }
    gridbar(gen);

    for (int tau = 0; tau < 201; tau++) {
        const bool doL0 = hasL0 && (tau < 200);
        const bool doL1 = hasL1 && (tau >= 1);

        if (doL0 || doL1) {
            const float* src = d_h1buf[(tau + 1) & 1];
            for (int idx = t; idx < 16384; idx += 256) {
                int bb = idx >> 9, k = idx & 511;
                bufA[bb * 516 + k] = __ldcg(&src[idx]);
            }
        }
        if (doL1) {
            const float* src = d_h2buf[tau & 1];
            for (int idx = t; idx < 16384; idx += 256) {
                int bb = idx >> 9, k = idx & 511;
                bufB[bb * 516 + k] = __ldcg(&src[idx]);
            }
        }
        __syncthreads();

        // ---- gate dot products ----
#pragma unroll
        for (int m = 0; m < 6; m++) {
            int u = cta * 6 + m;
            const float4* wrow;
            const float4* hv;
            bool act;
            if (u < 256) {
                act = (tau < 200);
                int col = t >> 5;                       // col = g*2 + dn
                int j = (col >> 1) * 512 + 2 * u + (col & 1);
                wrow = (const float4*)(Whh0 + (size_t)j * 512);
                hv = (const float4*)(bufA + b * 516);
            } else {
                act = (tau >= 1);
                int g = (t >> 5) & 3, half = t >> 7;
                int j = g * 512 + (u - 256);
                wrow = (const float4*)((half ? Whh1 : Wih1) + (size_t)j * 512);
                hv = (const float4*)((half ? bufB : bufA) + b * 516);
            }
            if (act) {
                float4 a0 = make_float4(0.f, 0.f, 0.f, 0.f);
                float4 a1 = make_float4(0.f, 0.f, 0.f, 0.f);
#pragma unroll 8
                for (int k4 = 0; k4 < 128; k4 += 2) {
                    float4 h0 = hv[k4], w0 = wrow[k4];
                    float4 h1v = hv[k4 + 1], w1 = wrow[k4 + 1];
                    a0.x = fmaf(h0.x, w0.x, a0.x); a0.y = fmaf(h0.y, w0.y, a0.y);
                    a0.z = fmaf(h0.z, w0.z, a0.z); a0.w = fmaf(h0.w, w0.w, a0.w);
                    a1.x = fmaf(h1v.x, w1.x, a1.x); a1.y = fmaf(h1v.y, w1.y, a1.y);
                    a1.z = fmaf(h1v.z, w1.z, a1.z); a1.w = fmaf(h1v.w, w1.w, a1.w);
                }
                g_sm[m * 256 + t] =
                    ((a0.x + a0.y) + (a0.z + a0.w)) + ((a1.x + a1.y) + (a1.z + a1.w));
            }
        }
        __syncthreads();

        // ---- cell updates ----
#pragma unroll
        for (int m = 0; m < 6; m++) {
            int u = cta * 6 + m;
            if (u < 256) {
                if (tau < 200 && t < 64) {
                    int dn = t >> 5, n = 2 * u + dn;
                    const float* g0 = &d_G0[(size_t)tau * 2048 * 32];
                    float gi = g0[(0 * 512 + n) * 32 + b] + g_sm[m * 256 + (0 + dn) * 32 + b];
                    float gf = g0[(1 * 512 + n) * 32 + b] + g_sm[m * 256 + (2 + dn) * 32 + b];
                    float gg = g0[(2 * 512 + n) * 32 + b] + g_sm[m * 256 + (4 + dn) * 32 + b];
                    float go = g0[(3 * 512 + n) * 32 + b] + g_sm[m * 256 + (6 + dn) * 32 + b];
                    float c = sigf(gf) * creg[m] + sigf(gi) * tanhf(gg);
                    creg[m] = c;
                    d_h1buf[tau & 1][b * 512 + n] = sigf(go) * tanhf(c);
                }
            } else {
                if (tau >= 1 && t < 32) {
                    int n = u - 256;
                    float gt[4];
#pragma unroll
                    for (int g = 0; g < 4; g++)
                        gt[g] = g_sm[m * 256 + g * 32 + t] + g_sm[m * 256 + 128 + g * 32 + t]
                              + bih1[g * 512 + n] + bhh1[g * 512 + n];
                    float c = sigf(gt[1]) * creg[m] + sigf(gt[0]) * tanhf(gt[2]);
                    creg[m] = c;
                    float h = sigf(gt[3]) * tanhf(c);
                    d_h2buf[(tau + 1) & 1][t * 512 + n] = h;
                    d_lstm[((size_t)t * Ss + (tau - 1)) * 512 + n] = h;
                }
            }
        }
        gridbar(gen);
    }
}

// =============== K_pred: per-row gathered head dot + BCE ====================
__global__ __launch_bounds__(256) void K_pred(
    const int* __restrict__ qt, const float* __restrict__ target,
    const float* __restrict__ rep, const float* __restrict__ past,
    const float* __restrict__ seq, const float* __restrict__ Wp,
    const float* __restrict__ bp, const float* __restrict__ C,
    float* __restrict__ out)
{
    int wid = (blockIdx.x * 256 + threadIdx.x) >> 5;
    int lane = threadIdx.x & 31;
    if (wid >= 6400) return;
    int r = wid;
    int b = r / Ss, s = r % Ss;
    int q = qt[r];
    const float* wrow = Wp + (size_t)q * 531;
    float acc = 0.f;
#pragma unroll
    for (int it = 0; it < 17; it++) {
        int idx = lane + 32 * it;
        if (idx < 531) {
            float v;
            if (idx < 512) {
                v = d_lstm[(size_t)r * 512 + idx];
            } else {
                int i = idx - 512;
                float craw;
                if (i < 7)       craw = rep[(b * (Ss + 1) + s + 1) * 7 + i];
                else if (i < 13) craw = seq[(b * (Ss + 1) + s + 1) * 6 + (i - 7)];
                else             craw = past[(b * (Ss + 1) + s + 1) * 6 + (i - 13)];
                v = C[(b * Ss + s) * 19 + i] * craw;
            }
            acc = fmaf(wrow[idx], v, acc);
        }
    }
#pragma unroll
    for (int o = 16; o > 0; o >>= 1) acc += __shfl_xor_sync(0xffffffffu, acc, o);
    if (lane == 0) {
        float p = 0.f, tm = 0.f, bce = 0.f;
        if (q > 0) {
            float x = acc + bp[q];
            p = 1.f / (1.f + expf(-x));
            float tt = target[r];
            bce = fmaxf(x, 0.f) - x * tt + log1pf(expf(-fabsf(x)));
            tm = tt;
        }
        out[1 + r] = p;
        out[1 + 6400 + r] = tm;
        d_bce[r] = bce;
    }
}

// ===================== K_loss: deterministic reduction ======================
__global__ void K_loss(const int* __restrict__ qt, float* __restrict__ out)
{
    __shared__ float s1[256], s2[256];
    int t = threadIdx.x;
    float a = 0.f, c = 0.f;
    for (int r = t; r < 6400; r += 256) {
        a += d_bce[r];
        c += (qt[r] > 0) ? 1.f : 0.f;
    }
    s1[t] = a; s2[t] = c;
    __syncthreads();
    for (int o = 128; o > 0; o >>= 1) {
        if (t < o) { s1[t] += s1[t + o]; s2[t] += s2[t + o]; }
        __syncthreads();
    }
    if (t == 0) out[0] = s1[0] / s2[0];
}

// ============================== launcher ====================================
extern "C" void kernel_launch(void* const* d_in, const int* in_sizes, int n_in,
                              void* d_out, int out_size)
{
    const int*   xd   = (const int*)  d_in[0];
    const int*   qt   = (const int*)  d_in[1];
    const float* tgt  = (const float*)d_in[2];
    const float* rep  = (const float*)d_in[3];
    const float* past = (const float*)d_in[4];
    const float* seq  = (const float*)d_in[5];
    const float* emb  = (const float*)d_in[6];
    const float* Wih0 = (const float*)d_in[7];
    const float* Whh0 = (const float*)d_in[8];
    const float* bih0 = (const float*)d_in[9];
    const float* bhh0 = (const float*)d_in[10];
    const float* Wih1 = (const float*)d_in[11];
    const float* Whh1 = (const float*)d_in[12];
    const float* bih1 = (const float*)d_in[13];
    const float* bhh1 = (const float*)d_in[14];
    const float* Wp   = (const float*)d_in[15];
    const float* bp   = (const float*)d_in[16];
    const float* C    = (const float*)d_in[17];
    const float* ih   = (const float*)d_in[18];
    const float* ic   = (const float*)d_in[19];
    float* out = (float*)d_out;

    const int smem_ig = (32 * ISTRIDE + 128 * WSTRIDE) * 4;   // 55,808 B
    const int smem_rc = 2 * 32 * 516 * 4;                     // 132,096 B
    cudaFuncSetAttribute(K_ingate, cudaFuncAttributeMaxDynamicSharedMemorySize, smem_ig);
    cudaFuncSetAttribute(K_recur,  cudaFuncAttributeMaxDynamicSharedMemorySize, smem_rc);

    dim3 gg(16, 200);
    K_ingate<<<gg, 256, smem_ig>>>(xd, rep, past, seq, emb, Wih0, bih0, bhh0, C);
    K_recur<<<NCTA, 256, smem_rc>>>(Whh0, Wih1, Whh1, bih1, bhh1, ih, ic);
    K_pred<<<800, 256>>>(qt, tgt, rep, past, seq, Wp, bp, C, out);
    K_loss<<<1, 256>>>(qt, out);
}

// round 11
// speedup vs baseline: 1.0028x; 1.0028x over previous
#include <cuda_runtime.h>
#include <math.h>

#define Bb 32
#define Ss 200
#define Hh 512
#define NCTA 128
#define ISTRIDE 292
#define WSTRIDE 36

// ------------------------- device scratch (static) -------------------------
__device__ float d_G0[6400 * 2048];     // [s][j][b] input-gate preacts + biases (52MB)
__device__ float d_h1buf[2][32 * 512];  // layer0 h, double buffered, [b][n]
__device__ float d_h2buf[2][32 * 512];  // layer1 h, double buffered, [b][n]
__device__ float d_lstm[6400 * 512];    // layer1 outputs, [(b*S+s)][n]
__device__ float d_bce[6400];
__device__ unsigned d_cnt = 0;
__device__ unsigned d_gen = 0;

__device__ __forceinline__ float sigf(float x) { return 1.f / (1.f + expf(-x)); }

// ===================== K_ingate: G0 = inp @ W_ih0^T + b =====================
// grid (16 j-tiles, 200 s), 256 threads. Tile 128j x 32b, per-thread 4x4.
__global__ __launch_bounds__(256) void K_ingate(
    const int* __restrict__ xd, const float* __restrict__ rep,
    const float* __restrict__ past, const float* __restrict__ seq,
    const float* __restrict__ emb, const float* __restrict__ Wih0,
    const float* __restrict__ bih0, const float* __restrict__ bhh0,
    const float* __restrict__ C)
{
    extern __shared__ float sh[];
    float* inp_sm = sh;                   // [32][ISTRIDE], zero-padded K: 275->288
    float* W_sm   = sh + 32 * ISTRIDE;    // [128][WSTRIDE] per k-tile
    const int t = threadIdx.x;
    const int s = blockIdx.y;
    const int j0 = blockIdx.x * 128;

    // stage input row-block for this s: [emb(x) | C * c_t], padded to 288
    for (int idx = t; idx < 32 * 288; idx += 256) {
        int b = idx / 288, k = idx % 288;
        float v = 0.f;
        if (k < 256) {
            int x = xd[b * Ss + s];
            v = emb[x * 256 + k];
        } else if (k < 275) {
            int i = k - 256;
            float craw;
            if (i < 7)       craw = rep[(b * (Ss + 1) + s) * 7 + i];
            else if (i < 13) craw = seq[(b * (Ss + 1) + s) * 6 + (i - 7)];
            else             craw = past[(b * (Ss + 1) + s) * 6 + (i - 13)];
            v = C[(b * Ss + s) * 19 + i] * craw;
        }
        inp_sm[b * ISTRIDE + k] = v;
    }

    float acc[4][4];
#pragma unroll
    for (int j = 0; j < 4; j++)
#pragma unroll
        for (int i = 0; i < 4; i++) acc[j][i] = 0.f;

    const int tx = t & 7;    // b = tx + 8*i
    const int ty = t >> 3;   // j = ty + 32*j

    for (int kt = 0; kt < 9; kt++) {
        __syncthreads();
        for (int idx = t; idx < 128 * 32; idx += 256) {
            int j = idx >> 5, kk = idx & 31, k = kt * 32 + kk;
            W_sm[j * WSTRIDE + kk] = (k < 275) ? Wih0[(j0 + j) * 275 + k] : 0.f;
        }
        __syncthreads();
#pragma unroll
        for (int k4 = 0; k4 < 8; k4++) {
            float4 a4[4], w4[4];
#pragma unroll
            for (int i = 0; i < 4; i++)
                a4[i] = *(const float4*)&inp_sm[(tx + 8 * i) * ISTRIDE + kt * 32 + k4 * 4];
#pragma unroll
            for (int j = 0; j < 4; j++)
                w4[j] = *(const float4*)&W_sm[(ty + 32 * j) * WSTRIDE + k4 * 4];
#pragma unroll
            for (int j = 0; j < 4; j++)
#pragma unroll
                for (int i = 0; i < 4; i++) {
                    acc[j][i] = fmaf(w4[j].x, a4[i].x, acc[j][i]);
                    acc[j][i] = fmaf(w4[j].y, a4[i].y, acc[j][i]);
                    acc[j][i] = fmaf(w4[j].z, a4[i].z, acc[j][i]);
                    acc[j][i] = fmaf(w4[j].w, a4[i].w, acc[j][i]);
                }
        }
    }
#pragma unroll
    for (int j = 0; j < 4; j++) {
        int jj = j0 + ty + 32 * j;
        float bias = bih0[jj] + bhh0[jj];
#pragma unroll
        for (int i = 0; i < 4; i++) {
            int b = tx + 8 * i;
            d_G0[((size_t)s * 2048 + jj) * 32 + b] = acc[j][i] + bias;
        }
    }
}

// ============================ grid barrier ==================================
__device__ __forceinline__ void gridbar(unsigned& gen)
{
    gen++;
    __syncthreads();
    __threadfence();
    if (threadIdx.x == 0) {
        unsigned a = atomicAdd(&d_cnt, 1u);
        if (a == NCTA - 1) {
            atomicExch(&d_cnt, 0u);
            __threadfence();
            atomicAdd(&d_gen, 1u);
        } else {
            while (atomicAdd(&d_gen, 0u) != gen) __nanosleep(40);
        }
    }
    __syncthreads();
    __threadfence();
}

// ========== K_recur: persistent 2-layer LSTM, software-pipelined ===========
// 768 equal-MAC gate-complete units: u<256 -> L0 (n0=2u, 8 cols x 32 b, K=512)
//                                    u>=256 -> L1 (n=u-256, 4g x 2half x 32 b, K=512)
// CTA i owns units 6i..6i+5. Superstep tau: L0 computes step tau, L1 step tau-1.
__global__ __launch_bounds__(256, 1) void K_recur(
    const float* __restrict__ Whh0, const float* __restrict__ Wih1,
    const float* __restrict__ Whh1, const float* __restrict__ bih1,
    const float* __restrict__ bhh1, const float* __restrict__ init_h,
    const float* __restrict__ init_c)
{
    extern __shared__ float sh[];
    float* bufA = sh;              // h1(prev step), [b][516]
    float* bufB = sh + 32 * 516;   // h2(prev-prev step), [b][516]
    __shared__ float g_sm[6 * 256];

    const int t = threadIdx.x, cta = blockIdx.x;
    const int b = t & 31;
    unsigned gen = atomicAdd(&d_gen, 0u);

    const bool hasL0 = (cta <= 42);
    const bool hasL1 = (cta >= 42);

    // cell state in registers of the updater threads
    float creg[6];
#pragma unroll
    for (int m = 0; m < 6; m++) {
        int u = cta * 6 + m;
        creg[m] = 0.f;
        if (u < 256) {
            if (t < 64) { int n = 2 * u + (t >> 5); creg[m] = init_c[b * 512 + n]; }
        } else {
            if (t < 32) { int n = u - 256; creg[m] = init_c[16384 + t * 512 + n]; }
        }
    }
    // init h double buffers (parity 1 = "step -1" state)
    {
        int gid = cta * 256 + t;
        if (gid < 16384) {
            d_h1buf[1][gid] = init_h[gid];
            d_h2buf[1][gid] = init_h[16384 + gid];
        }
    }
    gridbar(gen);

    for (int tau = 0; tau < 201; tau++) {
        const bool doL0 = hasL0 && (tau < 200);
        const bool doL1 = hasL1 && (tau >= 1);

        if (doL0 || doL1) {
            const float* src = d_h1buf[(tau + 1) & 1];
            for (int idx = t; idx < 16384; idx += 256) {
                int bb = idx >> 9, k = idx & 511;
                bufA[bb * 516 + k] = __ldcg(&src[idx]);
            }
        }
        if (doL1) {
            const float* src = d_h2buf[tau & 1];
            for (int idx = t; idx < 16384; idx += 256) {
                int bb = idx >> 9, k = idx & 511;
                bufB[bb * 516 + k] = __ldcg(&src[idx]);
            }
        }
        __syncthreads();

        // ---- gate dot products ----
#pragma unroll
        for (int m = 0; m < 6; m++) {
            int u = cta * 6 + m;
            const float4* wrow;
            const float4* hv;
            bool act;
            if (u < 256) {
                act = (tau < 200);
                int col = t >> 5;                       // col = g*2 + dn
                int j = (col >> 1) * 512 + 2 * u + (col & 1);
                wrow = (const float4*)(Whh0 + (size_t)j * 512);
                hv = (const float4*)(bufA + b * 516);
            } else {
                act = (tau >= 1);
                int g = (t >> 5) & 3, half = t >> 7;
                int j = g * 512 + (u - 256);
                wrow = (const float4*)((half ? Whh1 : Wih1) + (size_t)j * 512);
                hv = (const float4*)((half ? bufB : bufA) + b * 516);
            }
            if (act) {
                float4 a0 = make_float4(0.f, 0.f, 0.f, 0.f);
                float4 a1 = make_float4(0.f, 0.f, 0.f, 0.f);
#pragma unroll 8
                for (int k4 = 0; k4 < 128; k4 += 2) {
                    float4 h0 = hv[k4], w0 = wrow[k4];
                    float4 h1v = hv[k4 + 1], w1 = wrow[k4 + 1];
                    a0.x = fmaf(h0.x, w0.x, a0.x); a0.y = fmaf(h0.y, w0.y, a0.y);
                    a0.z = fmaf(h0.z, w0.z, a0.z); a0.w = fmaf(h0.w, w0.w, a0.w);
                    a1.x = fmaf(h1v.x, w1.x, a1.x); a1.y = fmaf(h1v.y, w1.y, a1.y);
                    a1.z = fmaf(h1v.z, w1.z, a1.z); a1.w = fmaf(h1v.w, w1.w, a1.w);
                }
                g_sm[m * 256 + t] =
                    ((a0.x + a0.y) + (a0.z + a0.w)) + ((a1.x + a1.y) + (a1.z + a1.w));
            }
        }
        __syncthreads();

        // ---- cell updates ----
#pragma unroll
        for (int m = 0; m < 6; m++) {
            int u = cta * 6 + m;
            if (u < 256) {
                if (tau < 200 && t < 64) {
                    int dn = t >> 5, n = 2 * u + dn;
                    const float* g0 = &d_G0[(size_t)tau * 2048 * 32];
                    float gi = g0[(0 * 512 + n) * 32 + b] + g_sm[m * 256 + (0 + dn) * 32 + b];
                    float gf = g0[(1 * 512 + n) * 32 + b] + g_sm[m * 256 + (2 + dn) * 32 + b];
                    float gg = g0[(2 * 512 + n) * 32 + b] + g_sm[m * 256 + (4 + dn) * 32 + b];
                    float go = g0[(3 * 512 + n) * 32 + b] + g_sm[m * 256 + (6 + dn) * 32 + b];
                    float c = sigf(gf) * creg[m] + sigf(gi) * tanhf(gg);
                    creg[m] = c;
                    d_h1buf[tau & 1][b * 512 + n] = sigf(go) * tanhf(c);
                }
            } else {
                if (tau >= 1 && t < 32) {
                    int n = u - 256;
                    float gt[4];
#pragma unroll
                    for (int g = 0; g < 4; g++)
                        gt[g] = g_sm[m * 256 + g * 32 + t] + g_sm[m * 256 + 128 + g * 32 + t]
                              + bih1[g * 512 + n] + bhh1[g * 512 + n];
                    float c = sigf(gt[1]) * creg[m] + sigf(gt[0]) * tanhf(gt[2]);
                    creg[m] = c;
                    float h = sigf(gt[3]) * tanhf(c);
                    d_h2buf[(tau + 1) & 1][t * 512 + n] = h;
                    d_lstm[((size_t)t * Ss + (tau - 1)) * 512 + n] = h;
                }
            }
        }
        gridbar(gen);
    }
}

// =============== K_pred: per-row gathered head dot + BCE ====================
__global__ __launch_bounds__(256) void K_pred(
    const int* __restrict__ qt, const float* __restrict__ target,
    const float* __restrict__ rep, const float* __restrict__ past,
    const float* __restrict__ seq, const float* __restrict__ Wp,
    const float* __restrict__ bp, const float* __restrict__ C,
    float* __restrict__ out)
{
    int wid = (blockIdx.x * 256 + threadIdx.x) >> 5;
    int lane = threadIdx.x & 31;
    if (wid >= 6400) return;
    int r = wid;
    int b = r / Ss, s = r % Ss;
    int q = qt[r];
    const float* wrow = Wp + (size_t)q * 531;
    float acc = 0.f;
#pragma unroll
    for (int it = 0; it < 17; it++) {
        int idx = lane + 32 * it;
        if (idx < 531) {
            float v;
            if (idx < 512) {
                v = d_lstm[(size_t)r * 512 + idx];
            } else {
                int i = idx - 512;
                float craw;
                if (i < 7)       craw = rep[(b * (Ss + 1) + s + 1) * 7 + i];
                else if (i < 13) craw = seq[(b * (Ss + 1) + s + 1) * 6 + (i - 7)];
                else             craw = past[(b * (Ss + 1) + s + 1) * 6 + (i - 13)];
                v = C[(b * Ss + s) * 19 + i] * craw;
            }
            acc = fmaf(wrow[idx], v, acc);
        }
    }
#pragma unroll
    for (int o = 16; o > 0; o >>= 1) acc += __shfl_xor_sync(0xffffffffu, acc, o);
    if (lane == 0) {
        float p = 0.f, tm = 0.f, bce = 0.f;
        if (q > 0) {
            float x = acc + bp[q];
            p = 1.f / (1.f + expf(-x));
            float tt = target[r];
            bce = fmaxf(x, 0.f) - x * tt + log1pf(expf(-fabsf(x)));
            tm = tt;
        }
        out[1 + r] = p;
        out[1 + 6400 + r] = tm;
        d_bce[r] = bce;
    }
}

// ===================== K_loss: deterministic reduction ======================
__global__ void K_loss(const int* __restrict__ qt, float* __restrict__ out)
{
    __shared__ float s1[256], s2[256];
    int t = threadIdx.x;
    float a = 0.f, c = 0.f;
    for (int r = t; r < 6400; r += 256) {
        a += d_bce[r];
        c += (qt[r] > 0) ? 1.f : 0.f;
    }
    s1[t] = a; s2[t] = c;
    __syncthreads();
    for (int o = 128; o > 0; o >>= 1) {
        if (t < o) { s1[t] += s1[t + o]; s2[t] += s2[t + o]; }
        __syncthreads();
    }
    if (t == 0) out[0] = s1[0] / s2[0];
}

// ============================== launcher ====================================
extern "C" void kernel_launch(void* const* d_in, const int* in_sizes, int n_in,
                              void* d_out, int out_size)
{
    const int*   xd   = (const int*)  d_in[0];
    const int*   qt   = (const int*)  d_in[1];
    const float* tgt  = (const float*)d_in[2];
    const float* rep  = (const float*)d_in[3];
    const float* past = (const float*)d_in[4];
    const float* seq  = (const float*)d_in[5];
    const float* emb  = (const float*)d_in[6];
    const float* Wih0 = (const float*)d_in[7];
    const float* Whh0 = (const float*)d_in[8];
    const float* bih0 = (const float*)d_in[9];
    const float* bhh0 = (const float*)d_in[10];
    const float* Wih1 = (const float*)d_in[11];
    const float* Whh1 = (const float*)d_in[12];
    const float* bih1 = (const float*)d_in[13];
    const float* bhh1 = (const float*)d_in[14];
    const float* Wp   = (const float*)d_in[15];
    const float* bp   = (const float*)d_in[16];
    const float* C    = (const float*)d_in[17];
    const float* ih   = (const float*)d_in[18];
    const float* ic   = (const float*)d_in[19];
    float* out = (float*)d_out;

    const int smem_ig = (32 * ISTRIDE + 128 * WSTRIDE) * 4;   // 55,808 B
    const int smem_rc = 2 * 32 * 516 * 4;                     // 132,096 B
    cudaFuncSetAttribute(K_ingate, cudaFuncAttributeMaxDynamicSharedMemorySize, smem_ig);
    cudaFuncSetAttribute(K_recur,  cudaFuncAttributeMaxDynamicSharedMemorySize, smem_rc);

    dim3 gg(16, 200);
    K_ingate<<<gg, 256, smem_ig>>>(xd, rep, past, seq, emb, Wih0, bih0, bhh0, C);
    K_recur<<<NCTA, 256, smem_rc>>>(Whh0, Wih1, Whh1, bih1, bhh1, ih, ic);
    K_pred<<<800, 256>>>(qt, tgt, rep, past, seq, Wp, bp, C, out);
    K_loss<<<1, 256>>>(qt, out);
}

// round 12
// speedup vs baseline: 1.9487x; 1.9433x over previous
#include <cuda_runtime.h>
#include <math.h>

#define Ss 200
#define NCTA 128
#define ISTRIDE 292
#define WSTRIDE 36
typedef unsigned long long u64;

__device__ float d_G0[6400 * 2048];
__device__ float d_h1buf[2][32 * 512];
__device__ float d_h2buf[2][32 * 512];
__device__ float d_lstm[6400 * 512];
__device__ float d_bce[6400];
__device__ unsigned d_cnt = 0;
__device__ unsigned d_gen = 0;

__device__ __forceinline__ float sigf(float x) { return 1.f / (1.f + expf(-x)); }
__device__ __forceinline__ void fma2(u64& d, u64 a, u64 b)
{ asm("fma.rn.f32x2 %0, %1, %2, %0;" : "+l"(d) : "l"(a), "l"(b)); }
__device__ __forceinline__ float sum2(u64 v)
{ float lo, hi; asm("mov.b64 {%0,%1}, %2;" : "=f"(lo), "=f"(hi) : "l"(v)); return lo + hi; }

// ===== K_ingate: G0[s][g*512+n][b] = inp @ W_ih0^T + bih0 + bhh0 =====
__global__ __launch_bounds__(256) void K_ingate(
    const int* __restrict__ xd, const float* __restrict__ rep,
    const float* __restrict__ past, const float* __restrict__ seq,
    const float* __restrict__ emb, const float* __restrict__ Wih0,
    const float* __restrict__ bih0, const float* __restrict__ bhh0,
    const float* __restrict__ C)
{
    extern __shared__ float sh[];
    float* inp_sm = sh;                 // [32][ISTRIDE]
    float* W_sm   = sh + 32 * ISTRIDE;  // [128][WSTRIDE]
    const int t = threadIdx.x, s = blockIdx.y, j0 = blockIdx.x * 128;

    for (int idx = t; idx < 32 * 288; idx += 256) {
        int b = idx / 288, k = idx % 288;
        float v = 0.f;
        if (k < 256) v = emb[xd[b * Ss + s] * 256 + k];
        else if (k < 275) {
            int i = k - 256; float craw;
            if (i < 7)       craw = rep[(b * (Ss + 1) + s) * 7 + i];
            else if (i < 13) craw = seq[(b * (Ss + 1) + s) * 6 + (i - 7)];
            else             craw = past[(b * (Ss + 1) + s) * 6 + (i - 13)];
            v = C[(b * Ss + s) * 19 + i] * craw;
        }
        inp_sm[b * ISTRIDE + k] = v;
    }
    float acc[4][4];
#pragma unroll
    for (int j = 0; j < 4; j++)
#pragma unroll
        for (int i = 0; i < 4; i++) acc[j][i] = 0.f;
    const int tx = t & 7, ty = t >> 3;
    for (int kt = 0; kt < 9; kt++) {
        __syncthreads();
        for (int idx = t; idx < 128 * 32; idx += 256) {
            int j = idx >> 5, kk = idx & 31, k = kt * 32 + kk;
            W_sm[j * WSTRIDE + kk] = (k < 275) ? Wih0[(j0 + j) * 275 + k] : 0.f;
        }
        __syncthreads();
#pragma unroll
        for (int k4 = 0; k4 < 8; k4++) {
            float4 a4[4], w4[4];
#pragma unroll
            for (int i = 0; i < 4; i++)
                a4[i] = *(const float4*)&inp_sm[(tx + 8 * i) * ISTRIDE + kt * 32 + k4 * 4];
#pragma unroll
            for (int j = 0; j < 4; j++)
                w4[j] = *(const float4*)&W_sm[(ty + 32 * j) * WSTRIDE + k4 * 4];
#pragma unroll
            for (int j = 0; j < 4; j++)
#pragma unroll
                for (int i = 0; i < 4; i++) {
                    acc[j][i] = fmaf(w4[j].x, a4[i].x, acc[j][i]);
                    acc[j][i] = fmaf(w4[j].y, a4[i].y, acc[j][i]);
                    acc[j][i] = fmaf(w4[j].z, a4[i].z, acc[j][i]);
                    acc[j][i] = fmaf(w4[j].w, a4[i].w, acc[j][i]);
                }
        }
    }
#pragma unroll
    for (int j = 0; j < 4; j++) {
        int jj = j0 + ty + 32 * j;
        float bias = bih0[jj] + bhh0[jj];
#pragma unroll
        for (int i = 0; i < 4; i++)
            d_G0[((size_t)s * 2048 + jj) * 32 + (tx + 8 * i)] = acc[j][i] + bias;
    }
}

__device__ __forceinline__ void gridbar(unsigned& gen)
{
    gen++;
    __syncthreads();
    __threadfence();
    if (threadIdx.x == 0) {
        if (atomicAdd(&d_cnt, 1u) == NCTA - 1) {
            atomicExch(&d_cnt, 0u);
            __threadfence();
            atomicAdd(&d_gen, 1u);
        } else {
            while (atomicAdd(&d_gen, 0u) != gen) __nanosleep(40);
        }
    }
    __syncthreads();
    __threadfence();
}

// ===== K_recur: persistent pipelined 2-layer LSTM, weights in smem =====
// CTA owns n = 4*cta..+3 for both layers. 24 rounds q=wid*3+r:
//  q<8  L0: nl=q>>1,bh=q&1; lane: bp=lane>>2,s=lane&3; b=bh*16+bp(+8); k seg s.
//  q>=8 L1: nl=(q-8)>>2,bq=(q-8)&3; bp=lane>>3,s=lane&7; half=s>>2,sub=s&3.
__global__ __launch_bounds__(256, 1) void K_recur(
    const float* __restrict__ Whh0, const float* __restrict__ Wih1,
    const float* __restrict__ Whh1, const float* __restrict__ bih1,
    const float* __restrict__ bhh1, const float* __restrict__ init_h,
    const float* __restrict__ init_c)
{
    extern __shared__ ulonglong2 sm[];
    ulonglong2* bufA = sm;          // h1(tau-1), [b][128f4], xor 4*(b&1)
    ulonglong2* bufB = sm + 4096;   // h2(tau-2), extra ^4
    ulonglong2* W0   = sm + 8192;   // [nl][g][128]
    ulonglong2* W1   = sm + 10240;  // [(nl*2+half)*516 + g*128 + k4]

    const int t = threadIdx.x, cta = blockIdx.x;
    const int wid = t >> 5, lane = t & 31, cbase = cta * 4;
    unsigned gen = atomicAdd(&d_gen, 0u);

    const float4* Whh0f = (const float4*)Whh0;
    const float4* Wih1f = (const float4*)Wih1;
    const float4* Whh1f = (const float4*)Whh1;
    for (int idx = t; idx < 2048; idx += 256) {
        int nl = idx >> 9, g = (idx >> 7) & 3, k4 = idx & 127;
        ((float4*)W0)[idx] = Whh0f[(size_t)(g * 512 + cbase + nl) * 128 + k4];
    }
    for (int idx = t; idx < 4096; idx += 256) {
        int nl = idx >> 10, half = (idx >> 9) & 1, g = (idx >> 7) & 3, k4 = idx & 127;
        const float4* src = half ? Whh1f : Wih1f;
        ((float4*)W1)[(nl * 2 + half) * 516 + g * 128 + k4] =
            src[(size_t)(g * 512 + cbase + nl) * 128 + k4];
    }

    float creg[3][2];
    int r_n[3], r_b0[3], r_b1[3], r_s[3];
    bool r_L0[3], r_red[3];
#pragma unroll
    for (int r = 0; r < 3; r++) {
        int q = wid * 3 + r;
        if (q < 8) {
            r_L0[r] = true;
            int bp = lane >> 2; r_s[r] = lane & 3;
            r_b0[r] = (q & 1) * 16 + bp; r_b1[r] = r_b0[r] + 8;
            r_n[r] = cbase + (q >> 1);
        } else {
            r_L0[r] = false;
            int qq = q - 8, bp = lane >> 3; r_s[r] = lane & 7;
            r_b0[r] = (qq & 3) * 8 + bp; r_b1[r] = r_b0[r] + 4;
            r_n[r] = cbase + (qq >> 2);
        }
        r_red[r] = (r_s[r] == 0);
        creg[r][0] = creg[r][1] = 0.f;
        if (r_red[r]) {
            int off = r_L0[r] ? 0 : 16384;
            creg[r][0] = init_c[off + r_b0[r] * 512 + r_n[r]];
            creg[r][1] = init_c[off + r_b1[r] * 512 + r_n[r]];
        }
    }
    {
        int gid = cta * 256 + t;
        if (gid < 16384) {
            d_h1buf[1][gid] = init_h[gid];
            d_h2buf[1][gid] = init_h[16384 + gid];
        }
    }
    gridbar(gen);

    for (int tau = 0; tau <= Ss; tau++) {
        const float4* srcA = (const float4*)d_h1buf[(tau + 1) & 1];
        for (int idx = t; idx < 4096; idx += 256) {
            int b = idx >> 7, k4 = idx & 127;
            ((float4*)bufA)[(b << 7) | (k4 ^ (4 * (b & 1)))] = __ldcg(srcA + idx);
        }
        if (tau >= 1) {
            const float4* srcB = (const float4*)d_h2buf[tau & 1];
            for (int idx = t; idx < 4096; idx += 256) {
                int b = idx >> 7, k4 = idx & 127;
                ((float4*)bufB)[(b << 7) | (k4 ^ (4 * (b & 1)) ^ 4)] = __ldcg(srcB + idx);
            }
        }
        __syncthreads();

#pragma unroll
        for (int r = 0; r < 3; r++) {
            bool act = r_L0[r] ? (tau < Ss) : (tau >= 1);
            if (act) {
                const int b0 = r_b0[r], b1 = r_b1[r], s = r_s[r];
                u64 acc[4][2];
#pragma unroll
                for (int g = 0; g < 4; g++) { acc[g][0] = 0ull; acc[g][1] = 0ull; }

                if (r_L0[r]) {
                    const ulonglong2* h0p = bufA + (b0 << 7);
                    const ulonglong2* h1p = bufA + (b1 << 7);
                    const int ka0 = 4 * (b0 & 1), ka1 = 4 * (b1 & 1);
                    const ulonglong2* wb = W0 + ((r_n[r] - cbase) << 9);
#pragma unroll 4
                    for (int i = 0; i < 32; i++) {
                        int k4 = s + 4 * i;
                        ulonglong2 hv0 = h0p[k4 ^ ka0];
                        ulonglong2 hv1 = h1p[k4 ^ ka1];
#pragma unroll
                        for (int g = 0; g < 4; g++) {
                            ulonglong2 w = wb[g * 128 + k4];
                            fma2(acc[g][0], hv0.x, w.x); fma2(acc[g][0], hv0.y, w.y);
                            fma2(acc[g][1], hv1.x, w.x); fma2(acc[g][1], hv1.y, w.y);
                        }
                    }
                } else {
                    const int half = s >> 2, sub = s & 3;
                    const ulonglong2* hb = half ? bufB : bufA;
                    const int kx = half ? 4 : 0;
                    const ulonglong2* h0p = hb + (b0 << 7);
                    const ulonglong2* h1p = hb + (b1 << 7);
                    const int ka0 = (4 * (b0 & 1)) ^ kx, ka1 = (4 * (b1 & 1)) ^ kx;
                    const ulonglong2* wb = W1 + (((r_n[r] - cbase) * 2 + half) * 516);
#pragma unroll 4
                    for (int i = 0; i < 32; i++) {
                        int k4 = sub + 4 * i;
                        ulonglong2 hv0 = h0p[k4 ^ ka0];
                        ulonglong2 hv1 = h1p[k4 ^ ka1];
#pragma unroll
                        for (int g = 0; g < 4; g++) {
                            ulonglong2 w = wb[g * 128 + k4];
                            fma2(acc[g][0], hv0.x, w.x); fma2(acc[g][0], hv0.y, w.y);
                            fma2(acc[g][1], hv1.x, w.x); fma2(acc[g][1], hv1.y, w.y);
                        }
                    }
                }

                float v[4][2];
#pragma unroll
                for (int g = 0; g < 4; g++) {
                    v[g][0] = sum2(acc[g][0]);
                    v[g][1] = sum2(acc[g][1]);
                }
                const int omax = r_L0[r] ? 4 : 8;
                for (int o = 1; o < omax; o <<= 1)
#pragma unroll
                    for (int g = 0; g < 4; g++) {
                        v[g][0] += __shfl_xor_sync(0xffffffffu, v[g][0], o);
                        v[g][1] += __shfl_xor_sync(0xffffffffu, v[g][1], o);
                    }

                if (r_red[r]) {
                    const int n = r_n[r];
                    if (r_L0[r]) {
                        const float* g0 = d_G0 + (size_t)tau * 65536;
#pragma unroll
                        for (int j = 0; j < 2; j++) {
                            int b = j ? r_b1[r] : r_b0[r];
                            float gi = v[0][j] + __ldcg(&g0[(0 * 512 + n) * 32 + b]);
                            float gf = v[1][j] + __ldcg(&g0[(1 * 512 + n) * 32 + b]);
                            float gg = v[2][j] + __ldcg(&g0[(2 * 512 + n) * 32 + b]);
                            float go = v[3][j] + __ldcg(&g0[(3 * 512 + n) * 32 + b]);
                            float c = sigf(gf) * creg[r][j] + sigf(gi) * tanhf(gg);
                            creg[r][j] = c;
                            d_h1buf[tau & 1][b * 512 + n] = sigf(go) * tanhf(c);
                        }
                    } else {
                        float bs[4];
#pragma unroll
                        for (int g = 0; g < 4; g++)
                            bs[g] = bih1[g * 512 + n] + bhh1[g * 512 + n];
#pragma unroll
                        for (int j = 0; j < 2; j++) {
                            int b = j ? r_b1[r] : r_b0[r];
                            float c = sigf(v[1][j] + bs[1]) * creg[r][j]
                                    + sigf(v[0][j] + bs[0]) * tanhf(v[2][j] + bs[2]);
                            creg[r][j] = c;
                            float h = sigf(v[3][j] + bs[3]) * tanhf(c);
                            d_h2buf[(tau + 1) & 1][b * 512 + n] = h;
                            d_lstm[((size_t)b * Ss + (tau - 1)) * 512 + n] = h;
                        }
                    }
                }
            }
        }
        gridbar(gen);
    }
}

// ===== K_pred: gathered head dot + BCE =====
__global__ __launch_bounds__(256) void K_pred(
    const int* __restrict__ qt, const float* __restrict__ target,
    const float* __restrict__ rep, const float* __restrict__ past,
    const float* __restrict__ seq, const float* __restrict__ Wp,
    const float* __restrict__ bp, const float* __restrict__ C,
    float* __restrict__ out)
{
    int r = (blockIdx.x * 256 + threadIdx.x) >> 5;
    int lane = threadIdx.x & 31;
    if (r >= 6400) return;
    int b = r / Ss, s = r % Ss, q = qt[r];
    const float* wrow = Wp + (size_t)q * 531;
    float acc = 0.f;
#pragma unroll
    for (int it = 0; it < 17; it++) {
        int idx = lane + 32 * it;
        if (idx < 531) {
            float v;
            if (idx < 512) v = d_lstm[(size_t)r * 512 + idx];
            else {
                int i = idx - 512; float craw;
                if (i < 7)       craw = rep[(b * (Ss + 1) + s + 1) * 7 + i];
                else if (i < 13) craw = seq[(b * (Ss + 1) + s + 1) * 6 + (i - 7)];
                else             craw = past[(b * (Ss + 1) + s + 1) * 6 + (i - 13)];
                v = C[(b * Ss + s) * 19 + i] * craw;
            }
            acc = fmaf(wrow[idx], v, acc);
        }
    }
#pragma unroll
    for (int o = 16; o > 0; o >>= 1) acc += __shfl_xor_sync(0xffffffffu, acc, o);
    if (lane == 0) {
        float p = 0.f, tm = 0.f, bce = 0.f;
        if (q > 0) {
            float x = acc + bp[q];
            p = 1.f / (1.f + expf(-x));
            float tt = target[r];
            bce = fmaxf(x, 0.f) - x * tt + log1pf(expf(-fabsf(x)));
            tm = tt;
        }
        out[1 + r] = p;
        out[1 + 6400 + r] = tm;
        d_bce[r] = bce;
    }
}

__global__ void K_loss(const int* __restrict__ qt, float* __restrict__ out)
{
    __shared__ float s1[256], s2[256];
    int t = threadIdx.x;
    float a = 0.f, c = 0.f;
    for (int r = t; r < 6400; r += 256) {
        a += d_bce[r];
        c += (qt[r] > 0) ? 1.f : 0.f;
    }
    s1[t] = a; s2[t] = c;
    __syncthreads();
    for (int o = 128; o > 0; o >>= 1) {
        if (t < o) { s1[t] += s1[t + o]; s2[t] += s2[t + o]; }
        __syncthreads();
    }
    if (t == 0) out[0] = s1[0] / s2[0];
}

extern "C" void kernel_launch(void* const* d_in, const int* in_sizes, int n_in,
                              void* d_out, int out_size)
{
    const int*   xd   = (const int*)  d_in[0];
    const int*   qt   = (const int*)  d_in[1];
    const float* tgt  = (const float*)d_in[2];
    const float* rep  = (const float*)d_in[3];
    const float* past = (const float*)d_in[4];
    const float* seq  = (const float*)d_in[5];
    const float* emb  = (const float*)d_in[6];
    const float* Wih0 = (const float*)d_in[7];
    const float* Whh0 = (const float*)d_in[8];
    const float* bih0 = (const float*)d_in[9];
    const float* bhh0 = (const float*)d_in[10];
    const float* Wih1 = (const float*)d_in[11];
    const float* Whh1 = (const float*)d_in[12];
    const float* bih1 = (const float*)d_in[13];
    const float* bhh1 = (const float*)d_in[14];
    const float* Wp   = (const float*)d_in[15];
    const float* bp   = (const float*)d_in[16];
    const float* C    = (const float*)d_in[17];
    const float* ih   = (const float*)d_in[18];
    const float* ic   = (const float*)d_in[19];
    float* out = (float*)d_out;

    const int smem_ig = (32 * ISTRIDE + 128 * WSTRIDE) * 4;
    const int smem_rc = 14368 * 16;  // 229,888 B
    cudaFuncSetAttribute(K_ingate, cudaFuncAttributeMaxDynamicSharedMemorySize, smem_ig);
    cudaFuncSetAttribute(K_recur,  cudaFuncAttributeMaxDynamicSharedMemorySize, smem_rc);

    dim3 gg(16, 200);
    K_ingate<<<gg, 256, smem_ig>>>(xd, rep, past, seq, emb, Wih0, bih0, bhh0, C);
    K_recur<<<NCTA, 256, smem_rc>>>(Whh0, Wih1, Whh1, bih1, bhh1, ih, ic);
    K_pred<<<800, 256>>>(qt, tgt, rep, past, seq, Wp, bp, C, out);
    K_loss<<<1, 256>>>(qt, out);
}

// round 14
// speedup vs baseline: 2.6772x; 1.3738x over previous
#include <cuda_runtime.h>
#include <math.h>

#define Ss 200
#define NCTA 128
#define ISTRIDE 292
#define WSTRIDE 36
typedef unsigned long long u64;

__device__ float d_G0[6400 * 2048];
__device__ float d_h1buf[2][32 * 512];
__device__ float d_h2buf[2][32 * 512];
__device__ float d_lstm[6400 * 512];
__device__ float d_bce[6400];
__device__ unsigned d_cnt = 0;
__device__ unsigned d_gen = 0;

__device__ __forceinline__ float sigf(float x) { return 1.f / (1.f + expf(-x)); }
__device__ __forceinline__ void fma2(u64& d, u64 a, u64 b)
{ asm("fma.rn.f32x2 %0, %1, %2, %0;" : "+l"(d) : "l"(a), "l"(b)); }
__device__ __forceinline__ float sum2(u64 v)
{ float lo, hi; asm("mov.b64 {%0,%1}, %2;" : "=f"(lo), "=f"(hi) : "l"(v)); return lo + hi; }

// ===== K_ingate: G0[s][g*512+n][b] = inp @ W_ih0^T + bih0 + bhh0 =====
__global__ __launch_bounds__(256) void K_ingate(
    const int* __restrict__ xd, const float* __restrict__ rep,
    const float* __restrict__ past, const float* __restrict__ seq,
    const float* __restrict__ emb, const float* __restrict__ Wih0,
    const float* __restrict__ bih0, const float* __restrict__ bhh0,
    const float* __restrict__ C)
{
    extern __shared__ float sh[];
    float* inp_sm = sh;                 // [32][ISTRIDE]
    float* W_sm   = sh + 32 * ISTRIDE;  // [128][WSTRIDE]
    const int t = threadIdx.x, s = blockIdx.y, j0 = blockIdx.x * 128;

    for (int idx = t; idx < 32 * 288; idx += 256) {
        int b = idx / 288, k = idx % 288;
        float v = 0.f;
        if (k < 256) v = emb[xd[b * Ss + s] * 256 + k];
        else if (k < 275) {
            int i = k - 256; float craw;
            if (i < 7)       craw = rep[(b * (Ss + 1) + s) * 7 + i];
            else if (i < 13) craw = seq[(b * (Ss + 1) + s) * 6 + (i - 7)];
            else             craw = past[(b * (Ss + 1) + s) * 6 + (i - 13)];
            v = C[(b * Ss + s) * 19 + i] * craw;
        }
        inp_sm[b * ISTRIDE + k] = v;
    }
    u64 acc[4][4];
#pragma unroll
    for (int j = 0; j < 4; j++)
#pragma unroll
        for (int i = 0; i < 4; i++) acc[j][i] = 0ull;
    const int tx = t & 7, ty = t >> 3;
    for (int kt = 0; kt < 9; kt++) {
        __syncthreads();
        for (int idx = t; idx < 128 * 32; idx += 256) {
            int j = idx >> 5, kk = idx & 31, k = kt * 32 + kk;
            W_sm[j * WSTRIDE + kk] = (k < 275) ? Wih0[(j0 + j) * 275 + k] : 0.f;
        }
        __syncthreads();
#pragma unroll
        for (int k4 = 0; k4 < 8; k4++) {
            ulonglong2 a2[4], w2[4];
#pragma unroll
            for (int i = 0; i < 4; i++)
                a2[i] = *(const ulonglong2*)&inp_sm[(tx + 8 * i) * ISTRIDE + kt * 32 + k4 * 4];
#pragma unroll
            for (int j = 0; j < 4; j++)
                w2[j] = *(const ulonglong2*)&W_sm[(ty + 32 * j) * WSTRIDE + k4 * 4];
#pragma unroll
            for (int j = 0; j < 4; j++)
#pragma unroll
                for (int i = 0; i < 4; i++) {
                    fma2(acc[j][i], w2[j].x, a2[i].x);
                    fma2(acc[j][i], w2[j].y, a2[i].y);
                }
        }
    }
#pragma unroll
    for (int j = 0; j < 4; j++) {
        int jj = j0 + ty + 32 * j;
        float bias = bih0[jj] + bhh0[jj];
#pragma unroll
        for (int i = 0; i < 4; i++)
            d_G0[((size_t)s * 2048 + jj) * 32 + (tx + 8 * i)] = sum2(acc[j][i]) + bias;
    }
}

__device__ __forceinline__ void gridbar(unsigned& gen)
{
    gen++;
    __syncthreads();
    __threadfence();
    if (threadIdx.x == 0) {
        if (atomicAdd(&d_cnt, 1u) == NCTA - 1) {
            atomicExch(&d_cnt, 0u);
            __threadfence();
            atomicAdd(&d_gen, 1u);
        } else {
            while (atomicAdd(&d_gen, 0u) != gen) __nanosleep(40);
        }
    }
    __syncthreads();
    __threadfence();
}

// ===== K_recur: persistent 2-layer LSTM; K-split warps, XOR-swizzled smem =====
// CTA owns n = 4*cta..+3 for both layers (16 ocols/layer, o = g*4+nl).
// Warps 0-3: L0, k4-chunk wid*32..+31 over bufA.  Warps 4-7: L1, half=(wid-4)>>1
// (0: Wih1 x bufA, 1: Whh1 x bufB), k4-chunk ((wid-4)&1)*64..+63.
// Lane og=lane>>3 (gate), bg=lane&7. Thread tile: o = og*4+i, b = bg+8j.
__global__ __launch_bounds__(256, 1) void K_recur(
    const float* __restrict__ Whh0, const float* __restrict__ Wih1,
    const float* __restrict__ Whh1, const float* __restrict__ bih1,
    const float* __restrict__ bhh1, const float* __restrict__ init_h,
    const float* __restrict__ init_c)
{
    extern __shared__ float4 smf4[];
    float4* bufA = smf4;            // h1(tau-1): [b][k4 ^ (b&7)]
    float4* bufB = smf4 + 4096;     // h2(tau-2)
    float4* W0   = smf4 + 8192;     // [o][k4 ^ (o>>2)]
    float4* W1   = smf4 + 10240;    // [half][o][k4 ^ (o>>2)]
    float* redL0 = (float*)bufA;    // aliased partials [w][o][b^(og<<3)] (post-sync)
    float* redL1 = (float*)bufB;

    const int t = threadIdx.x, cta = blockIdx.x, CB = cta * 4;
    const int wid = t >> 5, lane = t & 31;
    const int og = lane >> 3, bg = lane & 7;
    unsigned gen = atomicAdd(&d_gen, 0u);

    // ---- stage weights (once) ----
    const float4* Whh0f = (const float4*)Whh0;
    const float4* Wih1f = (const float4*)Wih1;
    const float4* Whh1f = (const float4*)Whh1;
    for (int idx = t; idx < 2048; idx += 256) {
        int o = idx >> 7, k4 = idx & 127, g = o >> 2, nl = o & 3;
        W0[o * 128 + (k4 ^ g)] = Whh0f[(size_t)(g * 512 + CB + nl) * 128 + k4];
    }
    for (int idx = t; idx < 4096; idx += 256) {
        int half = idx >> 11, o = (idx >> 7) & 15, k4 = idx & 127;
        int g = o >> 2, nl = o & 3;
        const float4* src = half ? Whh1f : Wih1f;
        W1[half * 2048 + o * 128 + (k4 ^ g)] =
            src[(size_t)(g * 512 + CB + nl) * 128 + k4];
    }

    // ---- epilogue role: t<128 -> L0 cell, else L1 cell (nl = (t&127)>>5, b = t&31) ----
    float creg;
    float bs0 = 0.f, bs1 = 0.f, bs2 = 0.f, bs3 = 0.f;
    {
        int nl = (t & 127) >> 5, b = t & 31;
        if (t < 128) creg = init_c[b * 512 + CB + nl];
        else {
            creg = init_c[16384 + b * 512 + CB + nl];
            bs0 = bih1[0 * 512 + CB + nl] + bhh1[0 * 512 + CB + nl];
            bs1 = bih1[1 * 512 + CB + nl] + bhh1[1 * 512 + CB + nl];
            bs2 = bih1[2 * 512 + CB + nl] + bhh1[2 * 512 + CB + nl];
            bs3 = bih1[3 * 512 + CB + nl] + bhh1[3 * 512 + CB + nl];
        }
    }
    {
        int gid = cta * 256 + t;
        if (gid < 16384) {
            d_h1buf[1][gid] = init_h[gid];
            d_h2buf[1][gid] = init_h[16384 + gid];
        }
    }
    gridbar(gen);

    for (int tau = 0; tau <= Ss; tau++) {
        // prefetch G0 for L0 epilogue
        float g0pf[4];
        if (t < 128 && tau < Ss) {
            int nl = t >> 5, b = t & 31;
            const float* g0 = d_G0 + (size_t)tau * 65536;
#pragma unroll
            for (int g = 0; g < 4; g++)
                g0pf[g] = __ldcg(&g0[(g * 512 + CB + nl) * 32 + b]);
        }
        // stage h (swizzled)
        const float4* srcA = (const float4*)d_h1buf[(tau + 1) & 1];
        for (int idx = t; idx < 4096; idx += 256) {
            int b = idx >> 7, k4 = idx & 127;
            bufA[b * 128 + (k4 ^ (b & 7))] = __ldcg(srcA + idx);
        }
        if (tau >= 1) {
            const float4* srcB = (const float4*)d_h2buf[tau & 1];
            for (int idx = t; idx < 4096; idx += 256) {
                int b = idx >> 7, k4 = idx & 127;
                bufB[b * 128 + (k4 ^ (b & 7))] = __ldcg(srcB + idx);
            }
        }
        __syncthreads();

        // ---- K-split gate GEMM ----
        const bool act = (wid < 4) ? (tau < Ss) : (tau >= 1);
        u64 acc[4][4];
        if (act) {
#pragma unroll
            for (int i = 0; i < 4; i++)
#pragma unroll
                for (int j = 0; j < 4; j++) acc[i][j] = 0ull;

            const float4* hbase;
            const float4* wbase;
            int k40, nk4;
            if (wid < 4) { hbase = bufA; wbase = W0; k40 = wid * 32; nk4 = 32; }
            else {
                int m = wid - 4, half = m >> 1;
                hbase = half ? bufB : bufA;
                wbase = W1 + half * 2048;
                k40 = (m & 1) * 64; nk4 = 64;
            }
            const float4* hp[4];
            const float4* wp[4];
#pragma unroll
            for (int j = 0; j < 4; j++) hp[j] = hbase + (bg + 8 * j) * 128;
#pragma unroll
            for (int i = 0; i < 4; i++) wp[i] = wbase + (og * 4 + i) * 128;

#pragma unroll 4
            for (int kk = 0; kk < nk4; kk++) {
                int k4 = k40 + kk;
                int kh = k4 ^ bg, kw = k4 ^ og;
                ulonglong2 h0 = *(const ulonglong2*)(hp[0] + kh);
                ulonglong2 h1 = *(const ulonglong2*)(hp[1] + kh);
                ulonglong2 h2 = *(const ulonglong2*)(hp[2] + kh);
                ulonglong2 h3 = *(const ulonglong2*)(hp[3] + kh);
#pragma unroll
                for (int i = 0; i < 4; i++) {
                    ulonglong2 w = *(const ulonglong2*)(wp[i] + kw);
                    fma2(acc[i][0], w.x, h0.x); fma2(acc[i][0], w.y, h0.y);
                    fma2(acc[i][1], w.x, h1.x); fma2(acc[i][1], w.y, h1.y);
                    fma2(acc[i][2], w.x, h2.x); fma2(acc[i][2], w.y, h2.y);
                    fma2(acc[i][3], w.x, h3.x); fma2(acc[i][3], w.y, h3.y);
                }
            }
        }
        __syncthreads();   // all k-loop reads of bufA/bufB done before red aliasing
        if (act) {
            float* red = (wid < 4) ? redL0 : redL1;
            int w4 = wid & 3;
#pragma unroll
            for (int i = 0; i < 4; i++) {
                int o = og * 4 + i;
#pragma unroll
                for (int j = 0; j < 4; j++) {
                    int b = bg + 8 * j;
                    red[w4 * 512 + o * 32 + (b ^ (og << 3))] = sum2(acc[i][j]);
                }
            }
        }
        __syncthreads();

        // ---- epilogue: one (nl,b) cell per thread ----
        if (t < 128) {
            if (tau < Ss) {
                int nl = t >> 5, b = t & 31;
                float gate[4];
#pragma unroll
                for (int g = 0; g < 4; g++) {
                    int ix = (g * 4 + nl) * 32 + (b ^ (g << 3));
                    gate[g] = redL0[ix] + redL0[512 + ix] + redL0[1024 + ix]
                            + redL0[1536 + ix] + g0pf[g];
                }
                float c = sigf(gate[1]) * creg + sigf(gate[0]) * tanhf(gate[2]);
                creg = c;
                d_h1buf[tau & 1][b * 512 + CB + nl] = sigf(gate[3]) * tanhf(c);
            }
        } else {
            if (tau >= 1) {
                int nl = (t & 127) >> 5, b = t & 31;
                float gate[4];
#pragma unroll
                for (int g = 0; g < 4; g++) {
                    int ix = (g * 4 + nl) * 32 + (b ^ (g << 3));
                    gate[g] = redL1[ix] + redL1[512 + ix] + redL1[1024 + ix]
                            + redL1[1536 + ix];
                }
                float c = sigf(gate[1] + bs1) * creg
                        + sigf(gate[0] + bs0) * tanhf(gate[2] + bs2);
                creg = c;
                float h = sigf(gate[3] + bs3) * tanhf(c);
                d_h2buf[(tau + 1) & 1][b * 512 + CB + nl] = h;
                d_lstm[((size_t)b * Ss + (tau - 1)) * 512 + CB + nl] = h;
            }
        }
        gridbar(gen);
    }
}

// ===== K_pred: gathered head dot + BCE =====
__global__ __launch_bounds__(256) void K_pred(
    const int* __restrict__ qt, const float* __restrict__ target,
    const float* __restrict__ rep, const float* __restrict__ past,
    const float* __restrict__ seq, const float* __restrict__ Wp,
    const float* __restrict__ bp, const float* __restrict__ C,
    float* __restrict__ out)
{
    int r = (blockIdx.x * 256 + threadIdx.x) >> 5;
    int lane = threadIdx.x & 31;
    if (r >= 6400) return;
    int b = r / Ss, s = r % Ss, q = qt[r];
    const float* wrow = Wp + (size_t)q * 531;
    float acc = 0.f;
#pragma unroll
    for (int it = 0; it < 17; it++) {
        int idx = lane + 32 * it;
        if (idx < 531) {
            float v;
            if (idx < 512) v = d_lstm[(size_t)r * 512 + idx];
            else {
                int i = idx - 512; float craw;
                if (i < 7)       craw = rep[(b * (Ss + 1) + s + 1) * 7 + i];
                else if (i < 13) craw = seq[(b * (Ss + 1) + s + 1) * 6 + (i - 7)];
                else             craw = past[(b * (Ss + 1) + s + 1) * 6 + (i - 13)];
                v = C[(b * Ss + s) * 19 + i] * craw;
            }
            acc = fmaf(wrow[idx], v, acc);
        }
    }
#pragma unroll
    for (int o = 16; o > 0; o >>= 1) acc += __shfl_xor_sync(0xffffffffu, acc, o);
    if (lane == 0) {
        float p = 0.f, tm = 0.f, bce = 0.f;
        if (q > 0) {
            float x = acc + bp[q];
            p = 1.f / (1.f + expf(-x));
            float tt = target[r];
            bce = fmaxf(x, 0.f) - x * tt + log1pf(expf(-fabsf(x)));
            tm = tt;
        }
        out[1 + r] = p;
        out[1 + 6400 + r] = tm;
        d_bce[r] = bce;
    }
}

__global__ void K_loss(const int* __restrict__ qt, float* __restrict__ out)
{
    __shared__ float s1[256], s2[256];
    int t = threadIdx.x;
    float a = 0.f, c = 0.f;
    for (int r = t; r < 6400; r += 256) {
        a += d_bce[r];
        c += (qt[r] > 0) ? 1.f : 0.f;
    }
    s1[t] = a; s2[t] = c;
    __syncthreads();
    for (int o = 128; o > 0; o >>= 1) {
        if (t < o) { s1[t] += s1[t + o]; s2[t] += s2[t + o]; }
        __syncthreads();
    }
    if (t == 0) out[0] = s1[0] / s2[0];
}

extern "C" void kernel_launch(void* const* d_in, const int* in_sizes, int n_in,
                              void* d_out, int out_size)
{
    const int*   xd   = (const int*)  d_in[0];
    const int*   qt   = (const int*)  d_in[1];
    const float* tgt  = (const float*)d_in[2];
    const float* rep  = (const float*)d_in[3];
    const float* past = (const float*)d_in[4];
    const float* seq  = (const float*)d_in[5];
    const float* emb  = (const float*)d_in[6];
    const float* Wih0 = (const float*)d_in[7];
    const float* Whh0 = (const float*)d_in[8];
    const float* bih0 = (const float*)d_in[9];
    const float* bhh0 = (const float*)d_in[10];
    const float* Wih1 = (const float*)d_in[11];
    const float* Whh1 = (const float*)d_in[12];
    const float* bih1 = (const float*)d_in[13];
    const float* bhh1 = (const float*)d_in[14];
    const float* Wp   = (const float*)d_in[15];
    const float* bp   = (const float*)d_in[16];
    const float* C    = (const float*)d_in[17];
    const float* ih   = (const float*)d_in[18];
    const float* ic   = (const float*)d_in[19];
    float* out = (float*)d_out;

    const int smem_ig = (32 * ISTRIDE + 128 * WSTRIDE) * 4;
    const int smem_rc = 14336 * 16;  // 229,376 B
    cudaFuncSetAttribute(K_ingate, cudaFuncAttributeMaxDynamicSharedMemorySize, smem_ig);
    cudaFuncSetAttribute(K_recur,  cudaFuncAttributeMaxDynamicSharedMemorySize, smem_rc);

    dim3 gg(16, 200);
    K_ingate<<<gg, 256, smem_ig>>>(xd, rep, past, seq, emb, Wih0, bih0, bhh0, C);
    K_recur<<<NCTA, 256, smem_rc>>>(Whh0, Wih1, Whh1, bih1, bhh1, ih, ic);
    K_pred<<<800, 256>>>(qt, tgt, rep, past, seq, Wp, bp, C, out);
    K_loss<<<1, 256>>>(qt, out);
}